// round 7
// baseline (speedup 1.0000x reference)
#include <cuda_runtime.h>
#include <cstdint>

// ACDA dynamic convolution via warp-level tf32 mma.sync.
// R7: W fragments moved to __device__ global (L2-resident) -> smem ~108KB -> 2 CTAs/SM.
// B fragments via conflict-free LDS from a padded smem x-row.
// Per (b,h): F[576,128px] = W_gen[576,64] @ X[64,128px]; bias+ReLU; 3x3 combine.

static constexpr int CH = 64, Hd = 128, Wdim = 128;
static constexpr int XSTR = 136;                         // xs row stride (floats): conflict-free frags

// smem layout (floats)
static constexpr int SM_XS   = 0;                        // [64][136]  = 8704 floats
static constexpr int SM_FS   = 64 * XSTR;                // [144][128] = 18432 floats
static constexpr int SM_BIAS = SM_FS + 144 * 128;        // [576]
static constexpr int SMEM_BYTES = (SM_BIAS + 576) * 4;   // 110848 B

__device__ uint32_t Wfrag_g[36 * 8 * 32 * 4];            // 144KB fragment-major tf32 W

static __device__ __forceinline__ uint32_t f2tf(float f) {
    uint32_t u;
    asm("cvt.rna.tf32.f32 %0, %1;" : "=r"(u) : "f"(f));
    return u;
}

static __device__ __forceinline__ void mma_tf32(float* d, const uint32_t* a, const uint32_t* b) {
    asm volatile(
        "mma.sync.aligned.m16n8k8.row.col.f32.tf32.tf32.f32 "
        "{%0,%1,%2,%3}, {%4,%5,%6,%7}, {%8,%9}, {%0,%1,%2,%3};"
        : "+f"(d[0]), "+f"(d[1]), "+f"(d[2]), "+f"(d[3])
        : "r"(a[0]), "r"(a[1]), "r"(a[2]), "r"(a[3]), "r"(b[0]), "r"(b[1]));
}

// Pack W_gen [576][64] into m16n8k8 A-fragment-major tf32 layout.
// a[r] at (row = lane/4 + 8*(r&1), col = lane%4 + 4*(r>>1))
__global__ void pack_w(const float* __restrict__ Wg) {
    int i = blockIdx.x * 256 + threadIdx.x;               // 0..36863
    int row = i >> 6, col = i & 63;
    int mt = row >> 4, rr = row & 15, ks = col >> 3, cc = col & 7;
    int ln = (rr & 7) * 4 + (cc & 3);
    int r  = (rr >> 3) + ((cc >> 2) << 1);
    Wfrag_g[((mt * 8 + ks) * 32 + ln) * 4 + r] = f2tf(Wg[i]);
}

__global__ __launch_bounds__(256, 2)
void acda_mma(const float* __restrict__ x,
              const float* __restrict__ bg,
              float* __restrict__ out,
              int nUnits)
{
    extern __shared__ float smem[];
    float* xs = smem + SM_XS;
    float* Fs = smem + SM_FS;
    float* bs = smem + SM_BIAS;

    const int t    = threadIdx.x;
    const int lane = t & 31;
    const int wid  = t >> 5;
    const int s     = wid & 3;    // n-strip: pixels [s*32, s*32+32)
    const int mhalf = wid >> 2;   // m-tile half within each chunk

    for (int i = t; i < 576; i += 256) bs[i] = bg[i];

    // epilogue mapping
    const int ecl = t >> 4;           // channel-within-chunk 0..15
    const int ew0 = (t & 15) * 8;     // pixel-group base

    // B-fragment smem coordinates (fixed per thread): value (c,px) at xs[c*XSTR+px]
    const int bpx = s * 32 + (lane >> 2);
    const int bc0 = lane & 3;

    for (int u = blockIdx.x; u < nUnits; u += gridDim.x) {
        const int b = u >> 7;
        const int h = u & 127;

        __syncthreads();   // prev unit epilogue done with xs

        // ---- stage x[b,:,h,:] into xs (coalesced, padded stride) ----
        {
            const float4* x4 = reinterpret_cast<const float4*>(
                x + (long)b * CH * Hd * Wdim + (long)h * Wdim);
            const long ch4 = (long)(Hd * Wdim / 4);
            #pragma unroll
            for (int i = 0; i < 8; i++) {
                int idx = i * 256 + t;
                int c = idx >> 5, w4 = idx & 31;
                float4 v = x4[(long)c * ch4 + w4];
                *reinterpret_cast<float4*>(&xs[c * XSTR + w4 * 4]) = v;
            }
        }
        __syncthreads();

        // ---- 4 chunks of 144 F-rows (16 channels = 9 m-tiles) ----
        #pragma unroll 1
        for (int ch = 0; ch < 4; ch++) {
            const int mtl0 = mhalf ? 5 : 0;
            const int mtlN = mhalf ? 4 : 5;
            #pragma unroll 1
            for (int i = 0; i < mtlN; i++) {
                const int mtl = mtl0 + i;
                const int mt  = ch * 9 + mtl;
                float acc[4][4];
                #pragma unroll
                for (int nt = 0; nt < 4; nt++)
                    #pragma unroll
                    for (int r = 0; r < 4; r++) acc[nt][r] = 0.f;

                // batched A-fragment loads from L2-resident global
                const uint4* Af = reinterpret_cast<const uint4*>(Wfrag_g) + (mt * 8) * 32 + lane;
                uint4 av[8];
                #pragma unroll
                for (int ks = 0; ks < 8; ks++) av[ks] = __ldg(Af + ks * 32);

                #pragma unroll
                for (int ks = 0; ks < 8; ks++) {
                    uint32_t a[4] = {av[ks].x, av[ks].y, av[ks].z, av[ks].w};
                    uint32_t bf[4][2];
                    #pragma unroll
                    for (int r = 0; r < 2; r++) {
                        const int c = ks * 8 + bc0 + 4 * r;
                        const float* xp = xs + c * XSTR + bpx;
                        #pragma unroll
                        for (int nt = 0; nt < 4; nt++)
                            bf[nt][r] = f2tf(xp[nt * 8]);
                    }
                    #pragma unroll
                    for (int nt = 0; nt < 4; nt++)
                        mma_tf32(acc[nt], a, bf[nt]);
                }

                // D: c[0,1] at (row lane/4, col 2*(lane%4)+{0,1}); c[2,3] at row+8
                const int row  = mtl * 16 + (lane >> 2);
                const int colb = s * 32 + 2 * (lane & 3);
                #pragma unroll
                for (int nt = 0; nt < 4; nt++) {
                    const int col = colb + nt * 8;
                    *reinterpret_cast<float2*>(&Fs[row * 128 + col]) =
                        make_float2(acc[nt][0], acc[nt][1]);
                    *reinterpret_cast<float2*>(&Fs[(row + 8) * 128 + col]) =
                        make_float2(acc[nt][2], acc[nt][3]);
                }
            }
            __syncthreads();   // F chunk complete

            // ---- bias + ReLU + 3x3 dynamic-filter combine ----
            const int c = ch * 16 + ecl;

            float o[8];
            #pragma unroll
            for (int j = 0; j < 8; j++) o[j] = 0.f;

            const float* xc = x + (long)(b * CH + c) * Hd * Wdim;
            #pragma unroll
            for (int dh = 0; dh < 3; dh++) {
                const int hh = h - 1 + dh;
                float row[10];
                if (dh == 1) {
                    const float* xr = xs + c * XSTR;      // center row from smem
                    #pragma unroll
                    for (int q = 0; q < 10; q++) {
                        int ww = ew0 - 1 + q;
                        row[q] = (ww >= 0 && ww < 128) ? xr[ww] : 0.f;
                    }
                } else if (hh >= 0 && hh < Hd) {
                    const float* xr = xc + (long)hh * Wdim;
                    #pragma unroll
                    for (int q = 0; q < 10; q++) {
                        int ww = ew0 - 1 + q;
                        row[q] = (ww >= 0 && ww < 128) ? __ldg(xr + ww) : 0.f;
                    }
                } else {
                    #pragma unroll
                    for (int q = 0; q < 10; q++) row[q] = 0.f;
                }
                #pragma unroll
                for (int p = 0; p < 3; p++) {
                    const int tap = dh * 3 + p;
                    const float bb = bs[c * 9 + tap];
                    const float* fRow = Fs + (ecl * 9 + tap) * 128 + ew0;
                    #pragma unroll
                    for (int j = 0; j < 8; j++) {
                        float f = fmaxf(fRow[j] + bb, 0.f);
                        o[j] = fmaf(f, row[j + p], o[j]);
                    }
                }
            }

            float* op = out + ((long)(b * CH + c) * Hd + h) * Wdim + ew0;
            *reinterpret_cast<float4*>(op)     = make_float4(o[0], o[1], o[2], o[3]);
            *reinterpret_cast<float4*>(op + 4) = make_float4(o[4], o[5], o[6], o[7]);

            __syncthreads();   // epilogue done reading Fs before next chunk overwrites
        }
    }
}

extern "C" void kernel_launch(void* const* d_in, const int* in_sizes, int n_in,
                              void* d_out, int out_size)
{
    const float* x  = (const float*)d_in[0];
    const float* Wg = (const float*)d_in[1];
    const float* bg = (const float*)d_in[2];
    float* out = (float*)d_out;

    const int B = in_sizes[0] / (CH * Hd * Wdim);
    const int nUnits = B * Hd;

    pack_w<<<144, 256>>>(Wg);

    cudaFuncSetAttribute(acda_mma, cudaFuncAttributeMaxDynamicSharedMemorySize, SMEM_BYTES);
    acda_mma<<<296, 256, SMEM_BYTES>>>(x, bg, out, nUnits);
}

// round 8
// speedup vs baseline: 1.6194x; 1.6194x over previous
#include <cuda_runtime.h>
#include <cstdint>

// ACDA dynamic convolution, tf32 mma.sync, warp-specialized producer/consumer.
// warps 0-3: GEMM F[576,128px] = W[576,64] @ X[64,128px] (B-frags in regs, A from smem W)
// warps 4-7: bias+ReLU + 3x3 dynamic-filter combine + store
// F handed off in double-buffered [144 rows][64 px] chunks via named barriers.

static constexpr int CH = 64, Hd = 128, Wdim = 128;
static constexpr int FSTR = 68;                       // Fs row stride (floats), anti-bank-conflict

// smem layout (bytes)
static constexpr int SM_W    = 0;                     // W frags: 36*8*32*16B = 147456
static constexpr int SM_F0   = 147456;                // F buf0: 144*68*4 = 39168
static constexpr int FBUF_B  = 144 * FSTR * 4;
static constexpr int SM_F1   = SM_F0 + FBUF_B;        // F buf1
static constexpr int SM_BIAS = SM_F1 + FBUF_B;        // 576 f32
static constexpr int SMEM_BYTES = SM_BIAS + 576 * 4;  // 228096

static __device__ __forceinline__ uint32_t f2tf(float f) {
    uint32_t u;
    asm("cvt.rna.tf32.f32 %0, %1;" : "=r"(u) : "f"(f));
    return u;
}

static __device__ __forceinline__ void mma_tf32(float* d, const uint32_t* a, const uint32_t* b) {
    asm volatile(
        "mma.sync.aligned.m16n8k8.row.col.f32.tf32.tf32.f32 "
        "{%0,%1,%2,%3}, {%4,%5,%6,%7}, {%8,%9}, {%0,%1,%2,%3};"
        : "+f"(d[0]), "+f"(d[1]), "+f"(d[2]), "+f"(d[3])
        : "r"(a[0]), "r"(a[1]), "r"(a[2]), "r"(a[3]), "r"(b[0]), "r"(b[1]));
}

// named barriers: FULL0=1 FULL1=2 EMPTY0=3 EMPTY1=4 (count 256 = 128 arrive + 128 sync)
static __device__ __forceinline__ void bar_sync_id(int id) {
    asm volatile("bar.sync %0, 256;" :: "r"(id) : "memory");
}
static __device__ __forceinline__ void bar_arrive_id(int id) {
    asm volatile("bar.arrive %0, 256;" :: "r"(id) : "memory");
}

__global__ __launch_bounds__(256, 1)
void acda_ws(const float* __restrict__ x,
             const float* __restrict__ Wg,
             const float* __restrict__ bg,
             float* __restrict__ out,
             int nUnits)
{
    extern __shared__ char smem[];
    uint32_t* Wf = reinterpret_cast<uint32_t*>(smem + SM_W);
    float*    bs = reinterpret_cast<float*>(smem + SM_BIAS);

    const int t    = threadIdx.x;
    const int lane = t & 31;
    const int wid  = t >> 5;

    // ---- stage W_gen as tf32 A-fragments (all 256 threads, once) ----
    // m16n8k8 A: a[r] at (row = lane/4 + 8*(r&1), col = lane%4 + 4*(r>>1))
    #pragma unroll 4
    for (int i = t; i < 576 * 64; i += 256) {
        int row = i >> 6, col = i & 63;
        int mt = row >> 4, rr = row & 15, ks = col >> 3, cc = col & 7;
        int ln = (rr & 7) * 4 + (cc & 3);
        int r  = (rr >> 3) + ((cc >> 2) << 1);
        Wf[((mt * 8 + ks) * 32 + ln) * 4 + r] = f2tf(Wg[i]);
    }
    for (int i = t; i < 576; i += 256) bs[i] = bg[i];
    __syncthreads();   // last bar-0 use before role divergence

    unsigned gchunk = 0;

    if (wid < 4) {
        // ================== PRODUCER (warps 0-3) ==================
        const int s     = wid >> 1;          // 32-px strip within the 64-px half
        const int mhalf = wid & 1;
        const int mtl0  = mhalf ? 5 : 0;
        const int mtlN  = mhalf ? 4 : 5;
        uint32_t bfr[4][8][2];               // B frags for current px-half

        for (int u = blockIdx.x; u < nUnits; u += gridDim.x) {
            const int b = u >> 7;
            const int h = u & 127;
            const float* xbh = x + (long)b * CH * Hd * Wdim + (long)h * Wdim;

            #pragma unroll 1
            for (int k = 0; k < 8; k++) {
                const int pxh = k >> 2, cg = k & 3;
                const int buf = (int)(gchunk & 1);

                if ((k & 3) == 0) {
                    // load B fragments for this px-half (B: b[r] at k=lane%4+4r, n=lane/4)
                    const int pxb = pxh * 64 + s * 32 + (lane >> 2);
                    #pragma unroll 1
                    for (int ks = 0; ks < 8; ks++) {
                        #pragma unroll
                        for (int r = 0; r < 2; r++) {
                            const int c = ks * 8 + (lane & 3) + 4 * r;
                            const float* xp = xbh + (long)c * Hd * Wdim + pxb;
                            #pragma unroll
                            for (int nt = 0; nt < 4; nt++)
                                bfr[nt][ks][r] = f2tf(__ldg(xp + nt * 8));
                        }
                    }
                }

                if (gchunk >= 2) bar_sync_id(3 + buf);   // wait buf freed

                float* fb = reinterpret_cast<float*>(smem + (buf ? SM_F1 : SM_F0));
                #pragma unroll 1
                for (int i2 = 0; i2 < mtlN; i2++) {
                    const int mtl = mtl0 + i2;
                    const int mt  = cg * 9 + mtl;
                    float acc[4][4];
                    #pragma unroll
                    for (int nt = 0; nt < 4; nt++)
                        #pragma unroll
                        for (int r = 0; r < 4; r++) acc[nt][r] = 0.f;

                    const uint4* Af = reinterpret_cast<const uint4*>(Wf) + (mt * 8) * 32 + lane;
                    uint4 av[8];
                    #pragma unroll
                    for (int ks = 0; ks < 8; ks++) av[ks] = Af[ks * 32];

                    #pragma unroll
                    for (int ks = 0; ks < 8; ks++) {
                        uint32_t a[4] = {av[ks].x, av[ks].y, av[ks].z, av[ks].w};
                        #pragma unroll
                        for (int nt = 0; nt < 4; nt++)
                            mma_tf32(acc[nt], a, bfr[nt][ks]);
                    }

                    // D: c[0,1] at (row lane/4, col 2*(lane%4)+{0,1}); c[2,3] at row+8
                    const int row  = mtl * 16 + (lane >> 2);
                    const int colb = s * 32 + 2 * (lane & 3);
                    #pragma unroll
                    for (int nt = 0; nt < 4; nt++) {
                        const int col = colb + nt * 8;
                        *reinterpret_cast<float2*>(&fb[row * FSTR + col]) =
                            make_float2(acc[nt][0], acc[nt][1]);
                        *reinterpret_cast<float2*>(&fb[(row + 8) * FSTR + col]) =
                            make_float2(acc[nt][2], acc[nt][3]);
                    }
                }

                __threadfence_block();       // STS visible before handoff
                bar_arrive_id(1 + buf);      // publish buf full
                gchunk++;
            }
        }
    } else {
        // ================== CONSUMER (warps 4-7) ==================
        const int wgt = t - 128;
        const int ecl = wgt >> 3;            // channel-within-chunk 0..15
        const int pw  = wgt & 7;             // 8-px group within the 64-px half

        for (int u = blockIdx.x; u < nUnits; u += gridDim.x) {
            const int b = u >> 7;
            const int h = u & 127;

            #pragma unroll 1
            for (int k = 0; k < 8; k++) {
                const int pxh = k >> 2, cg = k & 3;
                const int buf = (int)(gchunk & 1);

                bar_sync_id(1 + buf);        // wait buf full

                const float* fb = reinterpret_cast<const float*>(smem + (buf ? SM_F1 : SM_F0));
                const int c   = cg * 16 + ecl;
                const int px0 = pxh * 64 + pw * 8;

                float o[8];
                #pragma unroll
                for (int j = 0; j < 8; j++) o[j] = 0.f;

                const float* xc = x + (long)(b * CH + c) * Hd * Wdim;
                #pragma unroll
                for (int dh = 0; dh < 3; dh++) {
                    const int hh = h - 1 + dh;
                    float row[10];
                    if (hh >= 0 && hh < Hd) {
                        const float* xr = xc + (long)hh * Wdim;
                        #pragma unroll
                        for (int q = 0; q < 10; q++) {
                            int ww = px0 - 1 + q;
                            row[q] = (ww >= 0 && ww < 128) ? __ldg(xr + ww) : 0.f;
                        }
                    } else {
                        #pragma unroll
                        for (int q = 0; q < 10; q++) row[q] = 0.f;
                    }
                    #pragma unroll
                    for (int p = 0; p < 3; p++) {
                        const int tap = dh * 3 + p;
                        const float bb = bs[c * 9 + tap];
                        const float* fRow = fb + (ecl * 9 + tap) * FSTR + pw * 8;
                        #pragma unroll
                        for (int j = 0; j < 8; j++) {
                            float f = fmaxf(fRow[j] + bb, 0.f);
                            o[j] = fmaf(f, row[j + p], o[j]);
                        }
                    }
                }

                float* op = out + ((long)(b * CH + c) * Hd + h) * Wdim + px0;
                *reinterpret_cast<float4*>(op)     = make_float4(o[0], o[1], o[2], o[3]);
                *reinterpret_cast<float4*>(op + 4) = make_float4(o[4], o[5], o[6], o[7]);

                bar_arrive_id(3 + buf);      // publish buf free
                gchunk++;
            }
        }
    }
}

extern "C" void kernel_launch(void* const* d_in, const int* in_sizes, int n_in,
                              void* d_out, int out_size)
{
    const float* x  = (const float*)d_in[0];
    const float* Wg = (const float*)d_in[1];
    const float* bg = (const float*)d_in[2];
    float* out = (float*)d_out;

    const int B = in_sizes[0] / (CH * Hd * Wdim);
    const int nUnits = B * Hd;

    cudaFuncSetAttribute(acda_ws, cudaFuncAttributeMaxDynamicSharedMemorySize, SMEM_BYTES);
    acda_ws<<<148, 256, SMEM_BYTES>>>(x, Wg, bg, out, nUnits);
}

// round 9
// speedup vs baseline: 1.6522x; 1.0203x over previous
#include <cuda_runtime.h>
#include <cstdint>

// ACDA dynamic convolution, tf32 mma.sync, warp-specialized producer/consumer.
// R9: W fragments in __device__ global (L2-resident, batched LDG.128) -> smem = F bufs only
//     -> 2 CTAs/SM (16 warps) for latency hiding.
// warps 0-3: GEMM F[576,128px] = W[576,64] @ X[64,128px] (B-frags in regs)
// warps 4-7: bias+ReLU + 3x3 dynamic-filter combine + store
// F handed off in double-buffered [144 rows][64 px] chunks via named barriers.

static constexpr int CH = 64, Hd = 128, Wdim = 128;
static constexpr int FSTR = 68;                       // F row stride (floats), anti-bank-conflict

// smem layout (bytes)
static constexpr int SM_F0   = 0;
static constexpr int FBUF_B  = 144 * FSTR * 4;        // 39168
static constexpr int SM_F1   = SM_F0 + FBUF_B;
static constexpr int SM_BIAS = SM_F1 + FBUF_B;        // 576 f32
static constexpr int SMEM_BYTES = SM_BIAS + 576 * 4;  // 80640 -> 2 CTAs/SM

__device__ uint32_t Wfrag_g[36 * 8 * 32 * 4];         // 144KB fragment-major tf32 W

static __device__ __forceinline__ uint32_t f2tf(float f) {
    uint32_t u;
    asm("cvt.rna.tf32.f32 %0, %1;" : "=r"(u) : "f"(f));
    return u;
}

static __device__ __forceinline__ void mma_tf32(float* d, const uint32_t* a, const uint32_t* b) {
    asm volatile(
        "mma.sync.aligned.m16n8k8.row.col.f32.tf32.tf32.f32 "
        "{%0,%1,%2,%3}, {%4,%5,%6,%7}, {%8,%9}, {%0,%1,%2,%3};"
        : "+f"(d[0]), "+f"(d[1]), "+f"(d[2]), "+f"(d[3])
        : "r"(a[0]), "r"(a[1]), "r"(a[2]), "r"(a[3]), "r"(b[0]), "r"(b[1]));
}

// named barriers (per-CTA): FULL0=1 FULL1=2 EMPTY0=3 EMPTY1=4, count 256
static __device__ __forceinline__ void bar_sync_id(int id) {
    asm volatile("bar.sync %0, 256;" :: "r"(id) : "memory");
}
static __device__ __forceinline__ void bar_arrive_id(int id) {
    asm volatile("bar.arrive %0, 256;" :: "r"(id) : "memory");
}

// Pack W_gen [576][64] into m16n8k8 A-fragment-major tf32 layout.
// a[r] at (row = lane/4 + 8*(r&1), col = lane%4 + 4*(r>>1))
__global__ void pack_w(const float* __restrict__ Wg) {
    int i = blockIdx.x * 256 + threadIdx.x;            // 0..36863
    int row = i >> 6, col = i & 63;
    int mt = row >> 4, rr = row & 15, ks = col >> 3, cc = col & 7;
    int ln = (rr & 7) * 4 + (cc & 3);
    int r  = (rr >> 3) + ((cc >> 2) << 1);
    Wfrag_g[((mt * 8 + ks) * 32 + ln) * 4 + r] = f2tf(Wg[i]);
}

__global__ __launch_bounds__(256, 2)
void acda_ws(const float* __restrict__ x,
             const float* __restrict__ bg,
             float* __restrict__ out,
             int nUnits)
{
    extern __shared__ char smem[];
    float* bs = reinterpret_cast<float*>(smem + SM_BIAS);

    const int t    = threadIdx.x;
    const int lane = t & 31;
    const int wid  = t >> 5;

    for (int i = t; i < 576; i += 256) bs[i] = bg[i];
    __syncthreads();

    unsigned gchunk = 0;

    if (wid < 4) {
        // ================== PRODUCER (warps 0-3) ==================
        const int s     = wid >> 1;          // 32-px strip within the 64-px half
        const int mhalf = wid & 1;
        const int mtl0  = mhalf ? 5 : 0;
        const int mtlN  = mhalf ? 4 : 5;
        uint32_t bfr[4][8][2];               // B frags for current px-half

        for (int u = blockIdx.x; u < nUnits; u += gridDim.x) {
            const int b = u >> 7;
            const int h = u & 127;
            const float* xbh = x + (long)b * CH * Hd * Wdim + (long)h * Wdim;

            #pragma unroll 1
            for (int k = 0; k < 8; k++) {
                const int pxh = k >> 2, cg = k & 3;
                const int buf = (int)(gchunk & 1);

                if ((k & 3) == 0) {
                    // B fragments for this px-half (B: b[r] at k=lane%4+4r, n=lane/4)
                    const int pxb = pxh * 64 + s * 32 + (lane >> 2);
                    #pragma unroll 1
                    for (int ks = 0; ks < 8; ks++) {
                        #pragma unroll
                        for (int r = 0; r < 2; r++) {
                            const int c = ks * 8 + (lane & 3) + 4 * r;
                            const float* xp = xbh + (long)c * Hd * Wdim + pxb;
                            #pragma unroll
                            for (int nt = 0; nt < 4; nt++)
                                bfr[nt][ks][r] = f2tf(__ldg(xp + nt * 8));
                        }
                    }
                }

                if (gchunk >= 2) bar_sync_id(3 + buf);   // wait buf freed

                float* fb = reinterpret_cast<float*>(smem + (buf ? SM_F1 : SM_F0));
                #pragma unroll 1
                for (int i2 = 0; i2 < mtlN; i2++) {
                    const int mtl = mtl0 + i2;
                    const int mt  = cg * 9 + mtl;
                    float acc[4][4];
                    #pragma unroll
                    for (int nt = 0; nt < 4; nt++)
                        #pragma unroll
                        for (int r = 0; r < 4; r++) acc[nt][r] = 0.f;

                    // batched A-fragment loads from L2-resident global (8 LDG.128 in flight)
                    const uint4* Af = reinterpret_cast<const uint4*>(Wfrag_g) + (mt * 8) * 32 + lane;
                    uint4 av[8];
                    #pragma unroll
                    for (int ks = 0; ks < 8; ks++) av[ks] = __ldg(Af + ks * 32);

                    #pragma unroll
                    for (int ks = 0; ks < 8; ks++) {
                        uint32_t a[4] = {av[ks].x, av[ks].y, av[ks].z, av[ks].w};
                        #pragma unroll
                        for (int nt = 0; nt < 4; nt++)
                            mma_tf32(acc[nt], a, bfr[nt][ks]);
                    }

                    // D: c[0,1] at (row lane/4, col 2*(lane%4)+{0,1}); c[2,3] at row+8
                    const int row  = mtl * 16 + (lane >> 2);
                    const int colb = s * 32 + 2 * (lane & 3);
                    #pragma unroll
                    for (int nt = 0; nt < 4; nt++) {
                        const int col = colb + nt * 8;
                        *reinterpret_cast<float2*>(&fb[row * FSTR + col]) =
                            make_float2(acc[nt][0], acc[nt][1]);
                        *reinterpret_cast<float2*>(&fb[(row + 8) * FSTR + col]) =
                            make_float2(acc[nt][2], acc[nt][3]);
                    }
                }

                __threadfence_block();       // STS visible before handoff
                bar_arrive_id(1 + buf);      // publish buf full
                gchunk++;
            }
        }
    } else {
        // ================== CONSUMER (warps 4-7) ==================
        const int wgt = t - 128;
        const int ecl = wgt >> 3;            // channel-within-chunk 0..15
        const int pw  = wgt & 7;             // 8-px group within the 64-px half

        for (int u = blockIdx.x; u < nUnits; u += gridDim.x) {
            const int b = u >> 7;
            const int h = u & 127;

            #pragma unroll 1
            for (int k = 0; k < 8; k++) {
                const int pxh = k >> 2, cg = k & 3;
                const int buf = (int)(gchunk & 1);

                bar_sync_id(1 + buf);        // wait buf full

                const float* fb = reinterpret_cast<const float*>(smem + (buf ? SM_F1 : SM_F0));
                const int c   = cg * 16 + ecl;
                const int px0 = pxh * 64 + pw * 8;

                float o[8];
                #pragma unroll
                for (int j = 0; j < 8; j++) o[j] = 0.f;

                const float* xc = x + (long)(b * CH + c) * Hd * Wdim;
                #pragma unroll
                for (int dh = 0; dh < 3; dh++) {
                    const int hh = h - 1 + dh;
                    float row[10];
                    if (hh >= 0 && hh < Hd) {
                        const float* xr = xc + (long)hh * Wdim;
                        #pragma unroll
                        for (int q = 0; q < 10; q++) {
                            int ww = px0 - 1 + q;
                            row[q] = (ww >= 0 && ww < 128) ? __ldg(xr + ww) : 0.f;
                        }
                    } else {
                        #pragma unroll
                        for (int q = 0; q < 10; q++) row[q] = 0.f;
                    }
                    #pragma unroll
                    for (int p = 0; p < 3; p++) {
                        const int tap = dh * 3 + p;
                        const float bb = bs[c * 9 + tap];
                        const float* fRow = fb + (ecl * 9 + tap) * FSTR + pw * 8;
                        #pragma unroll
                        for (int j = 0; j < 8; j++) {
                            float f = fmaxf(fRow[j] + bb, 0.f);
                            o[j] = fmaf(f, row[j + p], o[j]);
                        }
                    }
                }

                float* op = out + ((long)(b * CH + c) * Hd + h) * Wdim + px0;
                *reinterpret_cast<float4*>(op)     = make_float4(o[0], o[1], o[2], o[3]);
                *reinterpret_cast<float4*>(op + 4) = make_float4(o[4], o[5], o[6], o[7]);

                bar_arrive_id(3 + buf);      // publish buf free
                gchunk++;
            }
        }
    }
}

extern "C" void kernel_launch(void* const* d_in, const int* in_sizes, int n_in,
                              void* d_out, int out_size)
{
    const float* x  = (const float*)d_in[0];
    const float* Wg = (const float*)d_in[1];
    const float* bg = (const float*)d_in[2];
    float* out = (float*)d_out;

    const int B = in_sizes[0] / (CH * Hd * Wdim);
    const int nUnits = B * Hd;

    pack_w<<<144, 256>>>(Wg);

    cudaFuncSetAttribute(acda_ws, cudaFuncAttributeMaxDynamicSharedMemorySize, SMEM_BYTES);
    acda_ws<<<296, 256, SMEM_BYTES>>>(x, bg, out, nUnits);
}

// round 16
// speedup vs baseline: 1.7625x; 1.0668x over previous
#include <cuda_runtime.h>
#include <cstdint>

// ACDA dynamic convolution, tf32 mma.sync, warp-specialized producer/consumer.
// R16 == R10 resubmit #6. Rounds 10-15 all died with broker/infra signatures
// (4x acquisition-timeout fired pre-ship — content-independent; 2x
// container-failed). Source audited three times: per-CTA named barriers with
// provably matched arrive/sync counts (no deadlock -> no container-killing
// hang), PTX feature set identical to the passing R6/R8/R9 kernels, smem
// (80640B) and regs (<=126) inside the (256,2) launch-bounds envelope.
// Design: half-unit work items (tail balance), consumer halo prefetch before
// the FULL barrier (overlaps producer MMA), W frags L2-resident, 2 CTAs/SM.
// warps 0-3: GEMM F-chunks [144ch-rows][64px]; warps 4-7: bias+ReLU+3x3 combine.

static constexpr int CH = 64, Hd = 128, Wdim = 128;
static constexpr int FSTR = 68;

// smem layout (bytes)
static constexpr int SM_F0   = 0;
static constexpr int FBUF_B  = 144 * FSTR * 4;        // 39168
static constexpr int SM_F1   = SM_F0 + FBUF_B;
static constexpr int SM_BIAS = SM_F1 + FBUF_B;
static constexpr int SMEM_BYTES = SM_BIAS + 576 * 4;  // 80640 -> 2 CTAs/SM

__device__ uint32_t Wfrag_g[36 * 8 * 32 * 4];         // 144KB fragment-major tf32 W

static __device__ __forceinline__ uint32_t f2tf(float f) {
    uint32_t u;
    asm("cvt.rna.tf32.f32 %0, %1;" : "=r"(u) : "f"(f));
    return u;
}

static __device__ __forceinline__ void mma_tf32(float* d, const uint32_t* a, const uint32_t* b) {
    asm volatile(
        "mma.sync.aligned.m16n8k8.row.col.f32.tf32.tf32.f32 "
        "{%0,%1,%2,%3}, {%4,%5,%6,%7}, {%8,%9}, {%0,%1,%2,%3};"
        : "+f"(d[0]), "+f"(d[1]), "+f"(d[2]), "+f"(d[3])
        : "r"(a[0]), "r"(a[1]), "r"(a[2]), "r"(a[3]), "r"(b[0]), "r"(b[1]));
}

// named barriers (per-CTA): FULL0=1 FULL1=2 EMPTY0=3 EMPTY1=4, count 256
static __device__ __forceinline__ void bar_sync_id(int id) {
    asm volatile("bar.sync %0, 256;" :: "r"(id) : "memory");
}
static __device__ __forceinline__ void bar_arrive_id(int id) {
    asm volatile("bar.arrive %0, 256;" :: "r"(id) : "memory");
}

// Pack W_gen [576][64] into m16n8k8 A-fragment-major tf32 layout.
// a[r] at (row = lane/4 + 8*(r&1), col = lane%4 + 4*(r>>1))
__global__ void pack_w(const float* __restrict__ Wg) {
    int i = blockIdx.x * 256 + threadIdx.x;            // 0..36863
    int row = i >> 6, col = i & 63;
    int mt = row >> 4, rr = row & 15, ks = col >> 3, cc = col & 7;
    int ln = (rr & 7) * 4 + (cc & 3);
    int r  = (rr >> 3) + ((cc >> 2) << 1);
    Wfrag_g[((mt * 8 + ks) * 32 + ln) * 4 + r] = f2tf(Wg[i]);
}

__global__ __launch_bounds__(256, 2)
void acda_ws(const float* __restrict__ x,
             const float* __restrict__ bg,
             float* __restrict__ out,
             int nItems)                               // = 2 * nUnits
{
    extern __shared__ char smem[];
    float* bs = reinterpret_cast<float*>(smem + SM_BIAS);

    const int t    = threadIdx.x;
    const int lane = t & 31;
    const int wid  = t >> 5;

    for (int i = t; i < 576; i += 256) bs[i] = bg[i];
    __syncthreads();

    unsigned gchunk = 0;

    if (wid < 4) {
        // ================== PRODUCER (warps 0-3) ==================
        const int s     = wid >> 1;          // 32-px strip within the item's 64-px half
        const int mhalf = wid & 1;
        const int mtl0  = mhalf ? 5 : 0;
        const int mtlN  = mhalf ? 4 : 5;
        uint32_t bfr[4][8][2];

        for (int it = blockIdx.x; it < nItems; it += gridDim.x) {
            const int u   = it >> 1;
            const int pxh = it & 1;
            const int b = u >> 7;
            const int h = u & 127;

            // B fragments for this item's 64-px half (issued before any barrier wait;
            // overlaps prior chunks' consumer drain). B: b[r] at k=lane%4+4r, n=lane/4.
            {
                const float* xbh = x + (long)b * CH * Hd * Wdim + (long)h * Wdim;
                const int pxb = pxh * 64 + s * 32 + (lane >> 2);
                #pragma unroll 1
                for (int ks = 0; ks < 8; ks++) {
                    #pragma unroll
                    for (int r = 0; r < 2; r++) {
                        const int c = ks * 8 + (lane & 3) + 4 * r;
                        const float* xp = xbh + (long)c * Hd * Wdim + pxb;
                        #pragma unroll
                        for (int nt = 0; nt < 4; nt++)
                            bfr[nt][ks][r] = f2tf(__ldg(xp + nt * 8));
                    }
                }
            }

            #pragma unroll 1
            for (int cg = 0; cg < 4; cg++) {
                const int buf = (int)(gchunk & 1);
                if (gchunk >= 2) bar_sync_id(3 + buf);   // wait buf freed

                float* fb = reinterpret_cast<float*>(smem + (buf ? SM_F1 : SM_F0));
                #pragma unroll 1
                for (int i2 = 0; i2 < mtlN; i2++) {
                    const int mtl = mtl0 + i2;
                    const int mt  = cg * 9 + mtl;
                    float acc[4][4];
                    #pragma unroll
                    for (int nt = 0; nt < 4; nt++)
                        #pragma unroll
                        for (int r = 0; r < 4; r++) acc[nt][r] = 0.f;

                    const uint4* Af = reinterpret_cast<const uint4*>(Wfrag_g) + (mt * 8) * 32 + lane;
                    uint4 av[8];
                    #pragma unroll
                    for (int ks = 0; ks < 8; ks++) av[ks] = __ldg(Af + ks * 32);

                    #pragma unroll
                    for (int ks = 0; ks < 8; ks++) {
                        uint32_t a[4] = {av[ks].x, av[ks].y, av[ks].z, av[ks].w};
                        #pragma unroll
                        for (int nt = 0; nt < 4; nt++)
                            mma_tf32(acc[nt], a, bfr[nt][ks]);
                    }

                    // D: c[0,1] at (row lane/4, col 2*(lane%4)+{0,1}); c[2,3] at row+8
                    const int row  = mtl * 16 + (lane >> 2);
                    const int colb = s * 32 + 2 * (lane & 3);
                    #pragma unroll
                    for (int nt = 0; nt < 4; nt++) {
                        const int col = colb + nt * 8;
                        *reinterpret_cast<float2*>(&fb[row * FSTR + col]) =
                            make_float2(acc[nt][0], acc[nt][1]);
                        *reinterpret_cast<float2*>(&fb[(row + 8) * FSTR + col]) =
                            make_float2(acc[nt][2], acc[nt][3]);
                    }
                }

                __threadfence_block();
                bar_arrive_id(1 + buf);      // publish buf full
                gchunk++;
            }
        }
    } else {
        // ================== CONSUMER (warps 4-7) ==================
        const int wgt = t - 128;
        const int ecl = wgt >> 3;            // channel-within-group 0..15
        const int pw  = wgt & 7;             // 8-px group within the 64-px half

        for (int it = blockIdx.x; it < nItems; it += gridDim.x) {
            const int u   = it >> 1;
            const int pxh = it & 1;
            const int b = u >> 7;
            const int h = u & 127;
            const int px0 = pxh * 64 + pw * 8;

            #pragma unroll 1
            for (int cg = 0; cg < 4; cg++) {
                const int buf = (int)(gchunk & 1);
                const int c = cg * 16 + ecl;

                // ---- halo prefetch (x only — independent of F) BEFORE the FULL wait ----
                float rowv[3][10];
                {
                    const float* xc = x + (long)(b * CH + c) * Hd * Wdim;
                    #pragma unroll
                    for (int dh = 0; dh < 3; dh++) {
                        const int hh = h - 1 + dh;
                        if (hh >= 0 && hh < Hd) {
                            const float* xr = xc + (long)hh * Wdim;
                            #pragma unroll
                            for (int q = 0; q < 10; q++) {
                                int ww = px0 - 1 + q;
                                rowv[dh][q] = (ww >= 0 && ww < 128) ? __ldg(xr + ww) : 0.f;
                            }
                        } else {
                            #pragma unroll
                            for (int q = 0; q < 10; q++) rowv[dh][q] = 0.f;
                        }
                    }
                }

                bar_sync_id(1 + buf);        // wait buf full (halo loads already in flight)

                const float* fb = reinterpret_cast<const float*>(smem + (buf ? SM_F1 : SM_F0));

                float o[8];
                #pragma unroll
                for (int j = 0; j < 8; j++) o[j] = 0.f;

                #pragma unroll
                for (int dh = 0; dh < 3; dh++) {
                    #pragma unroll
                    for (int p = 0; p < 3; p++) {
                        const int tap = dh * 3 + p;
                        const float bb = bs[c * 9 + tap];
                        const float* fRow = fb + (ecl * 9 + tap) * FSTR + pw * 8;
                        #pragma unroll
                        for (int j = 0; j < 8; j++) {
                            float f = fmaxf(fRow[j] + bb, 0.f);
                            o[j] = fmaf(f, rowv[dh][j + p], o[j]);
                        }
                    }
                }

                float* op = out + ((long)(b * CH + c) * Hd + h) * Wdim + px0;
                *reinterpret_cast<float4*>(op)     = make_float4(o[0], o[1], o[2], o[3]);
                *reinterpret_cast<float4*>(op + 4) = make_float4(o[4], o[5], o[6], o[7]);

                bar_arrive_id(3 + buf);      // publish buf free
                gchunk++;
            }
        }
    }
}

extern "C" void kernel_launch(void* const* d_in, const int* in_sizes, int n_in,
                              void* d_out, int out_size)
{
    const float* x  = (const float*)d_in[0];
    const float* Wg = (const float*)d_in[1];
    const float* bg = (const float*)d_in[2];
    float* out = (float*)d_out;

    const int B = in_sizes[0] / (CH * Hd * Wdim);
    const int nItems = B * Hd * 2;

    pack_w<<<144, 256>>>(Wg);

    cudaFuncSetAttribute(acda_ws, cudaFuncAttributeMaxDynamicSharedMemorySize, SMEM_BYTES);
    acda_ws<<<296, 256, SMEM_BYTES>>>(x, bg, out, nItems);
}

// round 17
// speedup vs baseline: 1.9469x; 1.1046x over previous
#include <cuda_runtime.h>
#include <cstdint>

// ACDA dynamic convolution, tf32 mma.sync, warp-specialized producer/consumer.
// R17 = R16 + vectorized consumer halo gather: 30 scalar LDG/thread/chunk ->
// 12 edge-predicated float4 LDG (coalesced per channel). Attacks the L1=66.7%
// wall ncu showed in R16. Producer and barrier protocol byte-identical to R16.
// warps 0-3: GEMM F-chunks [144ch-rows][64px]; warps 4-7: bias+ReLU+3x3 combine.

static constexpr int CH = 64, Hd = 128, Wdim = 128;
static constexpr int FSTR = 68;

// smem layout (bytes)
static constexpr int SM_F0   = 0;
static constexpr int FBUF_B  = 144 * FSTR * 4;        // 39168
static constexpr int SM_F1   = SM_F0 + FBUF_B;
static constexpr int SM_BIAS = SM_F1 + FBUF_B;
static constexpr int SMEM_BYTES = SM_BIAS + 576 * 4;  // 80640 -> 2 CTAs/SM

__device__ uint32_t Wfrag_g[36 * 8 * 32 * 4];         // 144KB fragment-major tf32 W

static __device__ __forceinline__ uint32_t f2tf(float f) {
    uint32_t u;
    asm("cvt.rna.tf32.f32 %0, %1;" : "=r"(u) : "f"(f));
    return u;
}

static __device__ __forceinline__ void mma_tf32(float* d, const uint32_t* a, const uint32_t* b) {
    asm volatile(
        "mma.sync.aligned.m16n8k8.row.col.f32.tf32.tf32.f32 "
        "{%0,%1,%2,%3}, {%4,%5,%6,%7}, {%8,%9}, {%0,%1,%2,%3};"
        : "+f"(d[0]), "+f"(d[1]), "+f"(d[2]), "+f"(d[3])
        : "r"(a[0]), "r"(a[1]), "r"(a[2]), "r"(a[3]), "r"(b[0]), "r"(b[1]));
}

// named barriers (per-CTA): FULL0=1 FULL1=2 EMPTY0=3 EMPTY1=4, count 256
static __device__ __forceinline__ void bar_sync_id(int id) {
    asm volatile("bar.sync %0, 256;" :: "r"(id) : "memory");
}
static __device__ __forceinline__ void bar_arrive_id(int id) {
    asm volatile("bar.arrive %0, 256;" :: "r"(id) : "memory");
}

// Pack W_gen [576][64] into m16n8k8 A-fragment-major tf32 layout.
// a[r] at (row = lane/4 + 8*(r&1), col = lane%4 + 4*(r>>1))
__global__ void pack_w(const float* __restrict__ Wg) {
    int i = blockIdx.x * 256 + threadIdx.x;            // 0..36863
    int row = i >> 6, col = i & 63;
    int mt = row >> 4, rr = row & 15, ks = col >> 3, cc = col & 7;
    int ln = (rr & 7) * 4 + (cc & 3);
    int r  = (rr >> 3) + ((cc >> 2) << 1);
    Wfrag_g[((mt * 8 + ks) * 32 + ln) * 4 + r] = f2tf(Wg[i]);
}

__global__ __launch_bounds__(256, 2)
void acda_ws(const float* __restrict__ x,
             const float* __restrict__ bg,
             float* __restrict__ out,
             int nItems)                               // = 2 * nUnits
{
    extern __shared__ char smem[];
    float* bs = reinterpret_cast<float*>(smem + SM_BIAS);

    const int t    = threadIdx.x;
    const int lane = t & 31;
    const int wid  = t >> 5;

    for (int i = t; i < 576; i += 256) bs[i] = bg[i];
    __syncthreads();

    unsigned gchunk = 0;

    if (wid < 4) {
        // ================== PRODUCER (warps 0-3) ==================
        const int s     = wid >> 1;          // 32-px strip within the item's 64-px half
        const int mhalf = wid & 1;
        const int mtl0  = mhalf ? 5 : 0;
        const int mtlN  = mhalf ? 4 : 5;
        uint32_t bfr[4][8][2];

        for (int it = blockIdx.x; it < nItems; it += gridDim.x) {
            const int u   = it >> 1;
            const int pxh = it & 1;
            const int b = u >> 7;
            const int h = u & 127;

            // B fragments for this item's 64-px half (issued before any barrier wait;
            // overlaps prior chunks' consumer drain). B: b[r] at k=lane%4+4r, n=lane/4.
            {
                const float* xbh = x + (long)b * CH * Hd * Wdim + (long)h * Wdim;
                const int pxb = pxh * 64 + s * 32 + (lane >> 2);
                #pragma unroll 1
                for (int ks = 0; ks < 8; ks++) {
                    #pragma unroll
                    for (int r = 0; r < 2; r++) {
                        const int c = ks * 8 + (lane & 3) + 4 * r;
                        const float* xp = xbh + (long)c * Hd * Wdim + pxb;
                        #pragma unroll
                        for (int nt = 0; nt < 4; nt++)
                            bfr[nt][ks][r] = f2tf(__ldg(xp + nt * 8));
                    }
                }
            }

            #pragma unroll 1
            for (int cg = 0; cg < 4; cg++) {
                const int buf = (int)(gchunk & 1);
                if (gchunk >= 2) bar_sync_id(3 + buf);   // wait buf freed

                float* fb = reinterpret_cast<float*>(smem + (buf ? SM_F1 : SM_F0));
                #pragma unroll 1
                for (int i2 = 0; i2 < mtlN; i2++) {
                    const int mtl = mtl0 + i2;
                    const int mt  = cg * 9 + mtl;
                    float acc[4][4];
                    #pragma unroll
                    for (int nt = 0; nt < 4; nt++)
                        #pragma unroll
                        for (int r = 0; r < 4; r++) acc[nt][r] = 0.f;

                    const uint4* Af = reinterpret_cast<const uint4*>(Wfrag_g) + (mt * 8) * 32 + lane;
                    uint4 av[8];
                    #pragma unroll
                    for (int ks = 0; ks < 8; ks++) av[ks] = __ldg(Af + ks * 32);

                    #pragma unroll
                    for (int ks = 0; ks < 8; ks++) {
                        uint32_t a[4] = {av[ks].x, av[ks].y, av[ks].z, av[ks].w};
                        #pragma unroll
                        for (int nt = 0; nt < 4; nt++)
                            mma_tf32(acc[nt], a, bfr[nt][ks]);
                    }

                    // D: c[0,1] at (row lane/4, col 2*(lane%4)+{0,1}); c[2,3] at row+8
                    const int row  = mtl * 16 + (lane >> 2);
                    const int colb = s * 32 + 2 * (lane & 3);
                    #pragma unroll
                    for (int nt = 0; nt < 4; nt++) {
                        const int col = colb + nt * 8;
                        *reinterpret_cast<float2*>(&fb[row * FSTR + col]) =
                            make_float2(acc[nt][0], acc[nt][1]);
                        *reinterpret_cast<float2*>(&fb[(row + 8) * FSTR + col]) =
                            make_float2(acc[nt][2], acc[nt][3]);
                    }
                }

                __threadfence_block();
                bar_arrive_id(1 + buf);      // publish buf full
                gchunk++;
            }
        }
    } else {
        // ================== CONSUMER (warps 4-7) ==================
        const int wgt = t - 128;
        const int ecl = wgt >> 3;            // channel-within-group 0..15
        const int pw  = wgt & 7;             // 8-px group within the 64-px half

        for (int it = blockIdx.x; it < nItems; it += gridDim.x) {
            const int u   = it >> 1;
            const int pxh = it & 1;
            const int b = u >> 7;
            const int h = u & 127;
            const int px0 = pxh * 64 + pw * 8;           // 0..120, multiple of 8
            const int q4  = px0 >> 2;                    // float4 index of px0

            #pragma unroll 1
            for (int cg = 0; cg < 4; cg++) {
                const int buf = (int)(gchunk & 1);
                const int c = cg * 16 + ecl;

                // ---- halo prefetch (x only), vectorized float4, BEFORE the FULL wait ----
                float rowv[3][10];
                {
                    const float* xc = x + (long)(b * CH + c) * Hd * Wdim;
                    const float4 z = make_float4(0.f, 0.f, 0.f, 0.f);
                    #pragma unroll
                    for (int dh = 0; dh < 3; dh++) {
                        const int hh = h - 1 + dh;
                        if (hh >= 0 && hh < Hd) {
                            const float4* xr4 =
                                reinterpret_cast<const float4*>(xc + (long)hh * Wdim);
                            // covers [px0-4, px0+12); edges predicated (and px0==0 /
                            // px0==120 loads skipped entirely: tensor-bounds safety)
                            float4 v0 = (px0 > 0)   ? __ldg(xr4 + q4 - 1) : z;
                            float4 v1 = __ldg(xr4 + q4);
                            float4 v2 = __ldg(xr4 + q4 + 1);
                            float4 v3 = (px0 < 120) ? __ldg(xr4 + q4 + 2) : z;
                            rowv[dh][0] = v0.w;
                            rowv[dh][1] = v1.x; rowv[dh][2] = v1.y;
                            rowv[dh][3] = v1.z; rowv[dh][4] = v1.w;
                            rowv[dh][5] = v2.x; rowv[dh][6] = v2.y;
                            rowv[dh][7] = v2.z; rowv[dh][8] = v2.w;
                            rowv[dh][9] = v3.x;
                        } else {
                            #pragma unroll
                            for (int q = 0; q < 10; q++) rowv[dh][q] = 0.f;
                        }
                    }
                }

                bar_sync_id(1 + buf);        // wait buf full (halo loads already in flight)

                const float* fb = reinterpret_cast<const float*>(smem + (buf ? SM_F1 : SM_F0));

                float o[8];
                #pragma unroll
                for (int j = 0; j < 8; j++) o[j] = 0.f;

                #pragma unroll
                for (int dh = 0; dh < 3; dh++) {
                    #pragma unroll
                    for (int p = 0; p < 3; p++) {
                        const int tap = dh * 3 + p;
                        const float bb = bs[c * 9 + tap];
                        const float* fRow = fb + (ecl * 9 + tap) * FSTR + pw * 8;
                        #pragma unroll
                        for (int j = 0; j < 8; j++) {
                            float f = fmaxf(fRow[j] + bb, 0.f);
                            o[j] = fmaf(f, rowv[dh][j + p], o[j]);
                        }
                    }
                }

                float* op = out + ((long)(b * CH + c) * Hd + h) * Wdim + px0;
                *reinterpret_cast<float4*>(op)     = make_float4(o[0], o[1], o[2], o[3]);
                *reinterpret_cast<float4*>(op + 4) = make_float4(o[4], o[5], o[6], o[7]);

                bar_arrive_id(3 + buf);      // publish buf free
                gchunk++;
            }
        }
    }
}

extern "C" void kernel_launch(void* const* d_in, const int* in_sizes, int n_in,
                              void* d_out, int out_size)
{
    const float* x  = (const float*)d_in[0];
    const float* Wg = (const float*)d_in[1];
    const float* bg = (const float*)d_in[2];
    float* out = (float*)d_out;

    const int B = in_sizes[0] / (CH * Hd * Wdim);
    const int nItems = B * Hd * 2;

    pack_w<<<144, 256>>>(Wg);

    cudaFuncSetAttribute(acda_ws, cudaFuncAttributeMaxDynamicSharedMemorySize, SMEM_BYTES);
    acda_ws<<<296, 256, SMEM_BYTES>>>(x, bg, out, nItems);
}